// round 2
// baseline (speedup 1.0000x reference)
#include <cuda_runtime.h>
#include <cuda_bf16.h>

#define B_   8
#define C_   64
#define H_   128
#define W_   416
#define CO2_ 144
#define OH_  (4 * H_)
#define OW_  (4 * W_)

// Scratch for the conv3x3+relu intermediate h: [B, 64, H, W] fp32 (~109 MB).
__device__ float g_h[B_ * C_ * H_ * W_];

// ---------------------------------------------------------------------------
// Kernel A: conv3x3 (pad=1, no bias) + ReLU.
// Block tile: 64 output channels x 64 x-positions at one (b, y).
// 128 threads, each computes 4 co x 8 x. ci processed in chunks of 8 via smem.
// Weights staged as sw[ci][tap][co] so 4 consecutive co -> one LDS.128.
// Per ci: 288 FMA vs ~39 LDS -> FFMA-issue bound.
// ---------------------------------------------------------------------------
__global__ __launch_bounds__(128) void conv3x3_relu_kernel(
    const float* __restrict__ feat, const float* __restrict__ w1)
{
    __shared__ float sf[8][3][66];   // feat chunk: 8 ci x 3 rows x (64+2) cols
    __shared__ float sw[8][9][64];   // weights:    8 ci x 9 taps x 64 co

    const int x0  = blockIdx.x * 64;
    const int y   = blockIdx.y;
    const int b   = blockIdx.z;
    const int tid = threadIdx.x;
    const int xg  = tid & 7;        // 8 x-groups
    const int cog = tid >> 3;       // 16 co-groups
    const int xl  = xg * 8;         // local x base (8 per thread)

    float acc[4][8];
    #pragma unroll
    for (int c = 0; c < 4; c++)
        #pragma unroll
        for (int x = 0; x < 8; x++) acc[c][x] = 0.f;

    for (int cc = 0; cc < C_; cc += 8) {
        // Stage feat chunk (zero-padded borders)
        for (int i = tid; i < 8 * 3 * 66; i += 128) {
            int ci  = i / 198;
            int rem = i - ci * 198;
            int ry  = rem / 66;
            int rx  = rem - ry * 66;
            int gy  = y + ry - 1;
            int gx  = x0 + rx - 1;
            float v = 0.f;
            if (gy >= 0 && gy < H_ && gx >= 0 && gx < W_)
                v = feat[((b * C_ + cc + ci) * H_ + gy) * W_ + gx];
            sf[ci][ry][rx] = v;
        }
        // Stage weight chunk transposed: sw[ci][tap][co] = w1[co][cc+ci][tap]
        for (int i = tid; i < 64 * 8 * 9; i += 128) {
            int co  = i / 72;
            int rem = i - co * 72;
            int ci  = rem / 9;
            int tap = rem - ci * 9;
            sw[ci][tap][co] = w1[co * (C_ * 9) + (cc + ci) * 9 + tap];
        }
        __syncthreads();

        #pragma unroll
        for (int ci = 0; ci < 8; ci++) {
            float f[3][10];
            #pragma unroll
            for (int r = 0; r < 3; r++)
                #pragma unroll
                for (int j = 0; j < 10; j++)
                    f[r][j] = sf[ci][r][xl + j];

            #pragma unroll
            for (int tap = 0; tap < 9; tap++) {
                const int ky = tap / 3;
                const int kx = tap - ky * 3;
                float4 w = *reinterpret_cast<const float4*>(&sw[ci][tap][cog * 4]);
                #pragma unroll
                for (int x = 0; x < 8; x++) {
                    float fv = f[ky][x + kx];
                    acc[0][x] = fmaf(w.x, fv, acc[0][x]);
                    acc[1][x] = fmaf(w.y, fv, acc[1][x]);
                    acc[2][x] = fmaf(w.z, fv, acc[2][x]);
                    acc[3][x] = fmaf(w.w, fv, acc[3][x]);
                }
            }
        }
        __syncthreads();
    }

    // ReLU + store to scratch
    #pragma unroll
    for (int c = 0; c < 4; c++) {
        const int co = cog * 4 + c;
        #pragma unroll
        for (int x = 0; x < 8; x++) {
            const int gx = x0 + xl + x;
            if (gx < W_)
                g_h[((b * C_ + co) * H_ + y) * W_ + gx] = fmaxf(acc[c][x], 0.f);
        }
    }
}

// ---------------------------------------------------------------------------
// Kernel B: 1x1 conv (64 -> 144) + softmax over 9 taps per (s1,s2) cell +
// 3x3 depth unfold blend + pixel shuffle, fully fused.
// Block: 32 pixels of one row (b, y); 256 threads.
// Thread (x, g): owns 2 cells (c0 = 2g, c1 = 2g+1), accumulates all 9 taps
// for each cell in registers -> softmax + blend in registers -> 2 outputs.
// w2 reads are warp-uniform (broadcast LDS); h reads are conflict-free.
// ---------------------------------------------------------------------------
__global__ __launch_bounds__(256) void mask_upsample_kernel(
    const float* __restrict__ depth, const float* __restrict__ w2,
    float* __restrict__ out)
{
    __shared__ float sh[64][32];     // h[ci][x] tile             (8 KB)
    __shared__ float sw2[64][144];   // w2 transposed [ci][co]    (36 KB)
    __shared__ float sdep[3][34];    // depth rows y-1..y+1, cols x0-1..x0+32

    const int x0  = blockIdx.x * 32;
    const int y   = blockIdx.y;
    const int b   = blockIdx.z;
    const int tid = threadIdx.x;
    const int x   = tid & 31;
    const int g   = tid >> 5;        // 0..7 -> cells 2g, 2g+1

    for (int i = tid; i < 64 * 32; i += 256) {
        int ci = i >> 5;
        int xx = i & 31;
        sh[ci][xx] = g_h[((b * C_ + ci) * H_ + y) * W_ + x0 + xx];
    }
    for (int i = tid; i < CO2_ * C_; i += 256) {
        int co = i >> 6;
        int ci = i & 63;
        sw2[ci][co] = w2[i];   // w2[co*64 + ci]
    }
    for (int i = tid; i < 3 * 34; i += 256) {
        int ry = i / 34;
        int rx = i - ry * 34;
        int gy = y + ry - 1;
        int gx = x0 + rx - 1;
        sdep[ry][rx] = (gy >= 0 && gy < H_ && gx >= 0 && gx < W_)
                       ? depth[(b * H_ + gy) * W_ + gx] : 0.f;
    }
    __syncthreads();

    const int c0 = 2 * g;
    const int c1 = 2 * g + 1;

    float a0[9], a1[9];
    #pragma unroll
    for (int t = 0; t < 9; t++) { a0[t] = 0.f; a1[t] = 0.f; }

    #pragma unroll 4
    for (int ci = 0; ci < 64; ci++) {
        float hv = sh[ci][x];
        #pragma unroll
        for (int t = 0; t < 9; t++) {
            a0[t] = fmaf(sw2[ci][t * 16 + c0], hv, a0[t]);
            a1[t] = fmaf(sw2[ci][t * 16 + c1], hv, a1[t]);
        }
    }

    // 3x3 depth patch for this pixel (tap = ky*3 + kx, row-major like torch unfold)
    float d[9];
    #pragma unroll
    for (int t = 0; t < 9; t++) d[t] = sdep[t / 3][x + (t % 3)];

    // Softmax over the 9 taps (per cell) + weighted depth blend
    float m0 = a0[0], m1 = a1[0];
    #pragma unroll
    for (int t = 1; t < 9; t++) { m0 = fmaxf(m0, a0[t]); m1 = fmaxf(m1, a1[t]); }
    float s0 = 0.f, v0 = 0.f, s1 = 0.f, v1 = 0.f;
    #pragma unroll
    for (int t = 0; t < 9; t++) {
        float e0 = __expf(a0[t] - m0);
        float e1 = __expf(a1[t] - m1);
        s0 += e0; v0 = fmaf(e0, d[t], v0);
        s1 += e1; v1 = fmaf(e1, d[t], v1);
    }
    v0 /= s0;
    v1 /= s1;

    // pixel shuffle: out[b, y*4 + s1, x*4 + s2], cell = s1*4 + s2
    const int ox = x0 + x;
    {
        int r0 = c0 >> 2, q0 = c0 & 3;
        out[((size_t)b * OH_ + (y * 4 + r0)) * OW_ + ox * 4 + q0] = v0;
        int r1 = c1 >> 2, q1 = c1 & 3;
        out[((size_t)b * OH_ + (y * 4 + r1)) * OW_ + ox * 4 + q1] = v1;
    }
}

extern "C" void kernel_launch(void* const* d_in, const int* in_sizes, int n_in,
                              void* d_out, int out_size)
{
    const float* depth = (const float*)d_in[0];
    const float* feat  = (const float*)d_in[1];
    const float* w1    = (const float*)d_in[2];
    const float* w2    = (const float*)d_in[3];
    float* out = (float*)d_out;

    dim3 gA((W_ + 63) / 64, H_, B_);     // 7 x 128 x 8
    conv3x3_relu_kernel<<<gA, 128>>>(feat, w1);

    dim3 gB(W_ / 32, H_, B_);            // 13 x 128 x 8
    mask_upsample_kernel<<<gB, 256>>>(depth, w2, out);
}

// round 5
// speedup vs baseline: 2.0804x; 2.0804x over previous
#include <cuda_runtime.h>
#include <cuda_bf16.h>
#include <cstdint>

#define B_   8
#define C_   64
#define H_   128
#define W_   416
#define OH_  (4 * H_)
#define OW_  (4 * W_)
#define HW_  (H_ * W_)

// Scratch for conv3x3+relu intermediate h: [B, 64, H, W] fp32 (~109 MB).
__device__ float g_h[B_ * C_ * H_ * W_];

// ---------------------------------------------------------------------------
// tf32 helpers (legacy mma.sync — compiles for plain compute_103)
// ---------------------------------------------------------------------------
__device__ __forceinline__ uint32_t f2tf32(float f) {
    uint32_t u;
    asm("cvt.rna.tf32.f32 %0, %1;" : "=r"(u) : "f"(f));
    return u;
}

__device__ __forceinline__ void mma_tf32(float* d, const uint32_t* a,
                                         uint32_t b0, uint32_t b1) {
    asm volatile(
        "mma.sync.aligned.m16n8k8.row.col.f32.tf32.tf32.f32 "
        "{%0,%1,%2,%3}, {%4,%5,%6,%7}, {%8,%9}, {%0,%1,%2,%3};"
        : "+f"(d[0]), "+f"(d[1]), "+f"(d[2]), "+f"(d[3])
        : "r"(a[0]), "r"(a[1]), "r"(a[2]), "r"(a[3]), "r"(b0), "r"(b1));
}

// ---------------------------------------------------------------------------
// Kernel A: conv3x3 (pad=1, no bias) + ReLU as tf32 implicit GEMM.
// CTA = 2 rows x 128 px x 64 co. M=256 (warp: 64 px of ONE row), N=64, K=576.
// smem: sfeat[4 rows][64 ci][136 pad] tf32 (139264 B)
//       swb[2 bufs][8 kchunk][64 co][4 pair][2] tf32 (32768 B), per-tap dbuf.
// Per k-chunk per warp: 16 LDS.32 (A) + 4 LDS.64 (B) + 16 HMMA.
// ---------------------------------------------------------------------------
#define OFF_WB   139264
#define SMEM_A_BYTES (139264 + 32768)

__device__ __forceinline__ void stage_w(uint32_t* dst, const float* __restrict__ w1,
                                        int tap, int tid) {
    for (int j = tid; j < 4096; j += 256) {
        int co = j >> 6, ci = j & 63;
        float v = w1[co * 576 + ci * 9 + tap];
        int kc = ci >> 3, kk = ci & 7;
        int p = kk & 3, slot = kk >> 2;
        dst[kc * 512 + co * 8 + p * 2 + slot] = f2tf32(v);
    }
}

__global__ __launch_bounds__(256, 1) void conv3x3_tc_kernel(
    const float* __restrict__ feat, const float* __restrict__ w1)
{
    extern __shared__ char sm[];
    uint32_t* sf = reinterpret_cast<uint32_t*>(sm);            // [4][64][136]
    uint32_t* sw = reinterpret_cast<uint32_t*>(sm + OFF_WB);   // [2][4096]

    const int x0  = blockIdx.x * 128;
    const int y0  = blockIdx.y * 2;
    const int b   = blockIdx.z;
    const int tid = threadIdx.x;
    const int wid = tid >> 5;
    const int lane = tid & 31;
    const int gid = lane >> 2;     // group id (rows of fragments)
    const int tig = lane & 3;      // thread-in-group (cols)

    const int warpM  = wid & 3;    // 4 M-warps: 0,1 -> row 0 ; 2,3 -> row 1
    const int warpN  = wid >> 2;   // 2 N-warps x 32 co
    const int rowsel = warpM >> 1;
    const int xwbase = (warpM & 1) * 64;

    // ---- Stage feat rows y0-1 .. y0+2, tf32, padded stride 136 ----
    for (int j = tid; j < 4 * 64 * 130; j += 256) {
        int r   = j / (64 * 130);
        int rem = j - r * (64 * 130);
        int ci  = rem / 130;
        int xi  = rem - ci * 130;
        int yy  = y0 + r - 1;
        int gx  = x0 + xi - 1;
        float v = 0.f;
        if ((unsigned)yy < (unsigned)H_ && (unsigned)gx < (unsigned)W_)
            v = feat[((size_t)(b * C_ + ci) * H_ + yy) * W_ + gx];
        sf[(r * 64 + ci) * 136 + xi] = f2tf32(v);
    }
    stage_w(sw, w1, 0, tid);
    __syncthreads();

    float acc[4][4][4];
    #pragma unroll
    for (int mf = 0; mf < 4; mf++)
        #pragma unroll
        for (int nf = 0; nf < 4; nf++)
            #pragma unroll
            for (int r = 0; r < 4; r++) acc[mf][nf][r] = 0.f;

    for (int t = 0; t < 9; t++) {
        if (t < 8) stage_w(sw + ((t + 1) & 1) * 4096, w1, t + 1, tid);
        const uint32_t* wb = sw + (t & 1) * 4096;
        const int ky = t / 3, kx = t - ky * 3;
        const uint32_t* frow = sf + (rowsel + ky) * 64 * 136;

        #pragma unroll
        for (int kc = 0; kc < 8; kc++) {
            uint32_t afr[4][4];
            #pragma unroll
            for (int mf = 0; mf < 4; mf++) {
                const uint32_t* ap = frow + (kc * 8 + tig) * 136
                                   + xwbase + mf * 16 + gid + kx;
                afr[mf][0] = ap[0];
                afr[mf][1] = ap[8];              // row gid+8
                afr[mf][2] = ap[4 * 136];        // ci +4
                afr[mf][3] = ap[4 * 136 + 8];
            }
            #pragma unroll
            for (int nf = 0; nf < 4; nf++) {
                int n = warpN * 32 + nf * 8 + gid;
                uint2 bb = *reinterpret_cast<const uint2*>(
                    wb + kc * 512 + n * 8 + tig * 2);
                #pragma unroll
                for (int mf = 0; mf < 4; mf++)
                    mma_tf32(acc[mf][nf], afr[mf], bb.x, bb.y);
            }
        }
        __syncthreads();
    }

    // ---- Epilogue: ReLU + store h. c0:(x,co) c1:(x,co+1) c2:(x+8,co) c3:(x+8,co+1)
    const int yy = y0 + rowsel;
    #pragma unroll
    for (int nf = 0; nf < 4; nf++) {
        const int co = warpN * 32 + nf * 8 + tig * 2;
        #pragma unroll
        for (int mf = 0; mf < 4; mf++) {
            const int xg = x0 + xwbase + mf * 16 + gid;
            size_t o = ((size_t)(b * C_ + co) * H_ + yy) * W_ + xg;
            if (xg < W_) {
                g_h[o]       = fmaxf(acc[mf][nf][0], 0.f);
                g_h[o + HW_] = fmaxf(acc[mf][nf][1], 0.f);
            }
            if (xg + 8 < W_) {
                g_h[o + 8]       = fmaxf(acc[mf][nf][2], 0.f);
                g_h[o + HW_ + 8] = fmaxf(acc[mf][nf][3], 0.f);
            }
        }
    }
}

// ---------------------------------------------------------------------------
// Kernel B: 1x1 conv (64 -> 144) + softmax over 9 taps + depth blend + shuffle.
// Block: 64 pixels of one row. 256 threads: thread = 1 cell (of 16) x 4 px.
// ---------------------------------------------------------------------------
#define SMEM_B_BYTES ((64 * 64 + 64 * 144 + 3 * 66) * 4)

__global__ __launch_bounds__(256) void mask_upsample_kernel(
    const float* __restrict__ depth, const float* __restrict__ w2,
    float* __restrict__ out)
{
    extern __shared__ float smb[];
    float (*sh)[64]   = reinterpret_cast<float(*)[64]>(smb);            // 16 KB
    float (*sw2)[144] = reinterpret_cast<float(*)[144]>(smb + 64 * 64); // 36 KB
    float (*sdep)[66] = reinterpret_cast<float(*)[66]>(smb + 64 * 64 + 64 * 144);

    const int x0   = blockIdx.x * 64;
    const int y    = blockIdx.y;
    const int b    = blockIdx.z;
    const int tid  = threadIdx.x;
    const int xg   = tid & 15;
    const int cell = tid >> 4;
    const int xl   = xg * 4;

    for (int i = tid; i < 64 * 64; i += 256) {
        int ci = i >> 6, xx = i & 63;
        int gx = x0 + xx;
        sh[ci][xx] = (gx < W_)
            ? g_h[((size_t)(b * C_ + ci) * H_ + y) * W_ + gx] : 0.f;
    }
    for (int i = tid; i < 144 * 64; i += 256) {
        int co = i >> 6, ci = i & 63;
        sw2[ci][co] = w2[i];
    }
    for (int i = tid; i < 3 * 66; i += 256) {
        int ry = i / 66, rx = i - ry * 66;
        int gy = y + ry - 1, gx = x0 + rx - 1;
        sdep[ry][rx] = (gy >= 0 && gy < H_ && gx >= 0 && gx < W_)
                       ? depth[((size_t)b * H_ + gy) * W_ + gx] : 0.f;
    }
    __syncthreads();

    float acc[4][9];
    #pragma unroll
    for (int j = 0; j < 4; j++)
        #pragma unroll
        for (int t = 0; t < 9; t++) acc[j][t] = 0.f;

    #pragma unroll 4
    for (int ci = 0; ci < 64; ci++) {
        float4 h4 = *reinterpret_cast<const float4*>(&sh[ci][xl]);
        float w[9];
        #pragma unroll
        for (int t = 0; t < 9; t++) w[t] = sw2[ci][t * 16 + cell];
        #pragma unroll
        for (int t = 0; t < 9; t++) {
            acc[0][t] = fmaf(w[t], h4.x, acc[0][t]);
            acc[1][t] = fmaf(w[t], h4.y, acc[1][t]);
            acc[2][t] = fmaf(w[t], h4.z, acc[2][t]);
            acc[3][t] = fmaf(w[t], h4.w, acc[3][t]);
        }
    }

    const int s1 = cell >> 2, s2 = cell & 3;
    #pragma unroll
    for (int j = 0; j < 4; j++) {
        float d[9];
        #pragma unroll
        for (int t = 0; t < 9; t++) d[t] = sdep[t / 3][xl + j + (t % 3)];
        float mx = acc[j][0];
        #pragma unroll
        for (int t = 1; t < 9; t++) mx = fmaxf(mx, acc[j][t]);
        float s = 0.f, v = 0.f;
        #pragma unroll
        for (int t = 0; t < 9; t++) {
            float e = __expf(acc[j][t] - mx);
            s += e;
            v = fmaf(e, d[t], v);
        }
        v /= s;
        int gx = x0 + xl + j;
        if (gx < W_)
            out[((size_t)b * OH_ + (y * 4 + s1)) * OW_ + gx * 4 + s2] = v;
    }
}

extern "C" void kernel_launch(void* const* d_in, const int* in_sizes, int n_in,
                              void* d_out, int out_size)
{
    const float* depth = (const float*)d_in[0];
    const float* feat  = (const float*)d_in[1];
    const float* w1    = (const float*)d_in[2];
    const float* w2    = (const float*)d_in[3];
    float* out = (float*)d_out;

    cudaFuncSetAttribute(conv3x3_tc_kernel,
                         cudaFuncAttributeMaxDynamicSharedMemorySize, SMEM_A_BYTES);
    cudaFuncSetAttribute(mask_upsample_kernel,
                         cudaFuncAttributeMaxDynamicSharedMemorySize, SMEM_B_BYTES);

    dim3 gA(4, H_ / 2, B_);                   // 4 x-tiles x 64 row-pairs x 8
    conv3x3_tc_kernel<<<gA, 256, SMEM_A_BYTES>>>(feat, w1);

    dim3 gB((W_ + 63) / 64, H_, B_);          // 7 x-tiles of 64 px
    mask_upsample_kernel<<<gB, 256, SMEM_B_BYTES>>>(depth, w2, out);
}

// round 6
// speedup vs baseline: 2.4530x; 1.1791x over previous
#include <cuda_runtime.h>
#include <cuda_bf16.h>
#include <cstdint>

#define B_   8
#define C_   64
#define H_   128
#define W_   416
#define OH_  (4 * H_)
#define OW_  (4 * W_)
#define HW_  (H_ * W_)

// Scratch for conv3x3+relu intermediate h: [B, 64, H, W] fp32 (~109 MB).
__device__ float g_h[B_ * C_ * H_ * W_];

// ---------------------------------------------------------------------------
// bf16 mma helper (legacy mma.sync m16n8k16 — compiles for plain compute_103)
// ---------------------------------------------------------------------------
__device__ __forceinline__ void mma_bf16(float* d, const uint32_t* a,
                                         uint32_t b0, uint32_t b1) {
    asm volatile(
        "mma.sync.aligned.m16n8k16.row.col.f32.bf16.bf16.f32 "
        "{%0,%1,%2,%3}, {%4,%5,%6,%7}, {%8,%9}, {%0,%1,%2,%3};"
        : "+f"(d[0]), "+f"(d[1]), "+f"(d[2]), "+f"(d[3])
        : "r"(a[0]), "r"(a[1]), "r"(a[2]), "r"(a[3]), "r"(b0), "r"(b1));
}

// ---------------------------------------------------------------------------
// Kernel A: conv3x3 (pad=1, no bias) + ReLU as bf16 implicit GEMM.
// CTA = 2 rows x 128 px x 64 co. 8 warps: 4 M-warps (64 px) x 2 N-warps (32 co).
// K per tap = 64 ci, 4 chunks of k=16.
// smem: sf[4 rows][130 x][72 ci-pad] bf16 (74880 B)  — pad 72: row step = 4
//       banks -> 8 fragment rows cover all 32 banks, conflict-free LDS.32.
//       sw[2 buf][64 co][72 ci-pad] bf16 (18432 B), per-tap double buffered.
// Total 93312 B -> 2 CTAs/SM.
// ---------------------------------------------------------------------------
#define SPADB  144              // bytes per ci-row (72 bf16)
#define OFF_W  74880
#define WBUF   9216
#define SMEM_A_BYTES (74880 + 2 * 9216)

__device__ __forceinline__ void stage_w(char* dst, const float* __restrict__ w1,
                                        int tap, int tid) {
    for (int j = tid; j < 2048; j += 256) {
        int co = j >> 5, ci2 = j & 31;
        const float* wp = w1 + co * 576 + ci2 * 18 + tap;
        __nv_bfloat162 v2 = __floats2bfloat162_rn(wp[0], wp[9]);
        *reinterpret_cast<uint32_t*>(dst + co * SPADB + ci2 * 4) =
            *reinterpret_cast<uint32_t*>(&v2);
    }
}

__global__ __launch_bounds__(256, 2) void conv3x3_tc_kernel(
    const float* __restrict__ feat, const float* __restrict__ w1)
{
    extern __shared__ char sm[];
    char* sf = sm;              // [4][130][72] bf16
    char* sw = sm + OFF_W;      // [2][64][72] bf16

    const int x0  = blockIdx.x * 128;
    const int y0  = blockIdx.y * 2;
    const int b   = blockIdx.z;
    const int tid = threadIdx.x;
    const int wid = tid >> 5;
    const int lane = tid & 31;
    const int gid = lane >> 2;
    const int tig = lane & 3;

    const int warpM  = wid & 3;
    const int warpN  = wid >> 2;
    const int rowsel = warpM >> 1;
    const int xwbase = (warpM & 1) * 64;

    // ---- Stage feat rows y0-1 .. y0+2 as bf16 pairs, layout [r][xi][ci] ----
    for (int j = tid; j < 4 * 32 * 130; j += 256) {
        int r   = j / (32 * 130);
        int rem = j - r * (32 * 130);
        int ci2 = rem / 130;
        int xi  = rem - ci2 * 130;
        int yy  = y0 + r - 1;
        int gx  = x0 + xi - 1;
        float f0 = 0.f, f1 = 0.f;
        if ((unsigned)yy < (unsigned)H_ && (unsigned)gx < (unsigned)W_) {
            size_t o = ((size_t)(b * C_ + 2 * ci2) * H_ + yy) * W_ + gx;
            f0 = feat[o];
            f1 = feat[o + (size_t)HW_];
        }
        __nv_bfloat162 v2 = __floats2bfloat162_rn(f0, f1);
        *reinterpret_cast<uint32_t*>(sf + (r * 130 + xi) * SPADB + ci2 * 4) =
            *reinterpret_cast<uint32_t*>(&v2);
    }
    stage_w(sw, w1, 0, tid);
    __syncthreads();

    float acc[4][4][4];
    #pragma unroll
    for (int mf = 0; mf < 4; mf++)
        #pragma unroll
        for (int nf = 0; nf < 4; nf++)
            #pragma unroll
            for (int r = 0; r < 4; r++) acc[mf][nf][r] = 0.f;

    for (int t = 0; t < 9; t++) {
        if (t < 8) stage_w(sw + ((t + 1) & 1) * WBUF, w1, t + 1, tid);
        const char* wb = sw + (t & 1) * WBUF;
        const int ky = t / 3, kx = t - ky * 3;
        const char* frow = sf + ((rowsel + ky) * 130) * SPADB;

        #pragma unroll
        for (int kc = 0; kc < 4; kc++) {
            uint32_t afr[4][4];
            #pragma unroll
            for (int mf = 0; mf < 4; mf++) {
                const char* ap = frow
                    + (xwbase + mf * 16 + gid + kx) * SPADB
                    + kc * 32 + tig * 4;
                afr[mf][0] = *reinterpret_cast<const uint32_t*>(ap);
                afr[mf][1] = *reinterpret_cast<const uint32_t*>(ap + 8 * SPADB);
                afr[mf][2] = *reinterpret_cast<const uint32_t*>(ap + 16);
                afr[mf][3] = *reinterpret_cast<const uint32_t*>(ap + 8 * SPADB + 16);
            }
            #pragma unroll
            for (int nf = 0; nf < 4; nf++) {
                const int n = warpN * 32 + nf * 8 + gid;
                const char* bp = wb + n * SPADB + kc * 32 + tig * 4;
                uint32_t b0 = *reinterpret_cast<const uint32_t*>(bp);
                uint32_t b1 = *reinterpret_cast<const uint32_t*>(bp + 16);
                #pragma unroll
                for (int mf = 0; mf < 4; mf++)
                    mma_bf16(acc[mf][nf], afr[mf], b0, b1);
            }
        }
        __syncthreads();
    }

    // ---- Epilogue: ReLU + store h. c0:(x,co) c1:(x,co+1) c2:(x+8,co) c3:(x+8,co+1)
    const int yy = y0 + rowsel;
    #pragma unroll
    for (int nf = 0; nf < 4; nf++) {
        const int co = warpN * 32 + nf * 8 + tig * 2;
        #pragma unroll
        for (int mf = 0; mf < 4; mf++) {
            const int xg = x0 + xwbase + mf * 16 + gid;
            size_t o = ((size_t)(b * C_ + co) * H_ + yy) * W_ + xg;
            if (xg < W_) {
                g_h[o]       = fmaxf(acc[mf][nf][0], 0.f);
                g_h[o + HW_] = fmaxf(acc[mf][nf][1], 0.f);
            }
            if (xg + 8 < W_) {
                g_h[o + 8]       = fmaxf(acc[mf][nf][2], 0.f);
                g_h[o + HW_ + 8] = fmaxf(acc[mf][nf][3], 0.f);
            }
        }
    }
}

// ---------------------------------------------------------------------------
// Kernel B: 1x1 conv (64 -> 144) + softmax over 9 taps + depth blend + shuffle.
// Block: 64 px of one row; 256 threads = 16 cells x 16 px-groups (4 px each).
// Weights re-laid out [ci][cell*12 + tap] so per-ci weight fetch is
// 2 x LDS.128 + 1 x LDS.32 (warp-broadcast, 2 cells) instead of 9 x LDS.32.
// ---------------------------------------------------------------------------
#define SMEM_B_BYTES ((64 * 64 + 64 * 192 + 3 * 66) * 4)

__global__ __launch_bounds__(256) void mask_upsample_kernel(
    const float* __restrict__ depth, const float* __restrict__ w2,
    float* __restrict__ out)
{
    extern __shared__ float smb[];
    float (*sh)[64]   = reinterpret_cast<float(*)[64]>(smb);             // 16 KB
    float (*swb)[192] = reinterpret_cast<float(*)[192]>(smb + 64 * 64);  // 48 KB
    float (*sdep)[66] = reinterpret_cast<float(*)[66]>(smb + 64 * 64 + 64 * 192);

    const int x0   = blockIdx.x * 64;
    const int y    = blockIdx.y;
    const int b    = blockIdx.z;
    const int tid  = threadIdx.x;
    const int xg   = tid & 15;
    const int cell = tid >> 4;
    const int xl   = xg * 4;

    for (int i = tid; i < 64 * 64; i += 256) {
        int ci = i >> 6, xx = i & 63;
        int gx = x0 + xx;
        sh[ci][xx] = (gx < W_)
            ? g_h[((size_t)(b * C_ + ci) * H_ + y) * W_ + gx] : 0.f;
    }
    // w2[co*64 + ci], co = t*16 + cell  ->  swb[ci][cell*12 + t]
    for (int j = tid; j < 144 * 64; j += 256) {
        int ci = j / 144;
        int co = j - ci * 144;
        int t = co >> 4, cl = co & 15;
        swb[ci][cl * 12 + t] = w2[co * 64 + ci];
    }
    for (int i = tid; i < 3 * 66; i += 256) {
        int ry = i / 66, rx = i - ry * 66;
        int gy = y + ry - 1, gx = x0 + rx - 1;
        sdep[ry][rx] = (gy >= 0 && gy < H_ && gx >= 0 && gx < W_)
                       ? depth[((size_t)b * H_ + gy) * W_ + gx] : 0.f;
    }
    __syncthreads();

    float acc[4][9];
    #pragma unroll
    for (int j = 0; j < 4; j++)
        #pragma unroll
        for (int t = 0; t < 9; t++) acc[j][t] = 0.f;

    const int wbase = cell * 12;
    #pragma unroll 4
    for (int ci = 0; ci < 64; ci++) {
        float4 h4 = *reinterpret_cast<const float4*>(&sh[ci][xl]);
        float4 wa = *reinterpret_cast<const float4*>(&swb[ci][wbase]);
        float4 wc = *reinterpret_cast<const float4*>(&swb[ci][wbase + 4]);
        float w8  = swb[ci][wbase + 8];
        float w[9] = {wa.x, wa.y, wa.z, wa.w, wc.x, wc.y, wc.z, wc.w, w8};
        #pragma unroll
        for (int t = 0; t < 9; t++) {
            acc[0][t] = fmaf(w[t], h4.x, acc[0][t]);
            acc[1][t] = fmaf(w[t], h4.y, acc[1][t]);
            acc[2][t] = fmaf(w[t], h4.z, acc[2][t]);
            acc[3][t] = fmaf(w[t], h4.w, acc[3][t]);
        }
    }

    const int s1 = cell >> 2, s2 = cell & 3;
    #pragma unroll
    for (int j = 0; j < 4; j++) {
        float d[9];
        #pragma unroll
        for (int t = 0; t < 9; t++) d[t] = sdep[t / 3][xl + j + (t % 3)];
        float mx = acc[j][0];
        #pragma unroll
        for (int t = 1; t < 9; t++) mx = fmaxf(mx, acc[j][t]);
        float s = 0.f, v = 0.f;
        #pragma unroll
        for (int t = 0; t < 9; t++) {
            float e = __expf(acc[j][t] - mx);
            s += e;
            v = fmaf(e, d[t], v);
        }
        v /= s;
        int gx = x0 + xl + j;
        if (gx < W_)
            out[((size_t)b * OH_ + (y * 4 + s1)) * OW_ + gx * 4 + s2] = v;
    }
}

extern "C" void kernel_launch(void* const* d_in, const int* in_sizes, int n_in,
                              void* d_out, int out_size)
{
    const float* depth = (const float*)d_in[0];
    const float* feat  = (const float*)d_in[1];
    const float* w1    = (const float*)d_in[2];
    const float* w2    = (const float*)d_in[3];
    float* out = (float*)d_out;

    cudaFuncSetAttribute(conv3x3_tc_kernel,
                         cudaFuncAttributeMaxDynamicSharedMemorySize, SMEM_A_BYTES);
    cudaFuncSetAttribute(mask_upsample_kernel,
                         cudaFuncAttributeMaxDynamicSharedMemorySize, SMEM_B_BYTES);

    dim3 gA(4, H_ / 2, B_);                   // 4 x-tiles x 64 row-pairs x 8
    conv3x3_tc_kernel<<<gA, 256, SMEM_A_BYTES>>>(feat, w1);

    dim3 gB((W_ + 63) / 64, H_, B_);          // 7 x-tiles of 64 px
    mask_upsample_kernel<<<gB, 256, SMEM_B_BYTES>>>(depth, w2, out);
}

// round 7
// speedup vs baseline: 4.7647x; 1.9424x over previous
#include <cuda_runtime.h>
#include <cuda_bf16.h>
#include <cstdint>

#define B_   8
#define C_   64
#define H_   128
#define W_   416
#define OH_  (4 * H_)
#define OW_  (4 * W_)
#define HW_  (H_ * W_)

// Scratch h: conv3x3+relu output, CHANNEL-LAST bf16: [b][y][x][ci] (~54.5 MB).
__device__ __nv_bfloat16 g_h[(size_t)B_ * H_ * W_ * C_];

// ---------------------------------------------------------------------------
// bf16 mma helper (legacy mma.sync m16n8k16 — compiles for plain compute_103)
// ---------------------------------------------------------------------------
__device__ __forceinline__ void mma_bf16(float* d, const uint32_t* a,
                                         uint32_t b0, uint32_t b1) {
    asm volatile(
        "mma.sync.aligned.m16n8k16.row.col.f32.bf16.bf16.f32 "
        "{%0,%1,%2,%3}, {%4,%5,%6,%7}, {%8,%9}, {%0,%1,%2,%3};"
        : "+f"(d[0]), "+f"(d[1]), "+f"(d[2]), "+f"(d[3])
        : "r"(a[0]), "r"(a[1]), "r"(a[2]), "r"(a[3]), "r"(b0), "r"(b1));
}

// ---------------------------------------------------------------------------
// Kernel A: conv3x3 (pad=1, no bias) + ReLU as bf16 implicit GEMM.
// CTA = 2 rows x 128 px x 64 co. 8 warps: 4 M-warps (64 px) x 2 N-warps (32 co).
// ---------------------------------------------------------------------------
#define SPADB  144              // bytes per ci-row (72 bf16)
#define OFF_W  74880
#define WBUF   9216
#define SMEM_A_BYTES (74880 + 2 * 9216)

__device__ __forceinline__ void stage_w(char* dst, const float* __restrict__ w1,
                                        int tap, int tid) {
    for (int j = tid; j < 2048; j += 256) {
        int co = j >> 5, ci2 = j & 31;
        const float* wp = w1 + co * 576 + ci2 * 18 + tap;
        __nv_bfloat162 v2 = __floats2bfloat162_rn(wp[0], wp[9]);
        *reinterpret_cast<uint32_t*>(dst + co * SPADB + ci2 * 4) =
            *reinterpret_cast<uint32_t*>(&v2);
    }
}

__global__ __launch_bounds__(256, 2) void conv3x3_tc_kernel(
    const float* __restrict__ feat, const float* __restrict__ w1)
{
    extern __shared__ char sm[];
    char* sf = sm;              // [4][130][72] bf16
    char* sw = sm + OFF_W;      // [2][64][72] bf16

    const int x0  = blockIdx.x * 128;
    const int y0  = blockIdx.y * 2;
    const int b   = blockIdx.z;
    const int tid = threadIdx.x;
    const int wid = tid >> 5;
    const int lane = tid & 31;
    const int gid = lane >> 2;
    const int tig = lane & 3;

    const int warpM  = wid & 3;
    const int warpN  = wid >> 2;
    const int rowsel = warpM >> 1;
    const int xwbase = (warpM & 1) * 64;

    for (int j = tid; j < 4 * 32 * 130; j += 256) {
        int r   = j / (32 * 130);
        int rem = j - r * (32 * 130);
        int ci2 = rem / 130;
        int xi  = rem - ci2 * 130;
        int yy  = y0 + r - 1;
        int gx  = x0 + xi - 1;
        float f0 = 0.f, f1 = 0.f;
        if ((unsigned)yy < (unsigned)H_ && (unsigned)gx < (unsigned)W_) {
            size_t o = ((size_t)(b * C_ + 2 * ci2) * H_ + yy) * W_ + gx;
            f0 = feat[o];
            f1 = feat[o + (size_t)HW_];
        }
        __nv_bfloat162 v2 = __floats2bfloat162_rn(f0, f1);
        *reinterpret_cast<uint32_t*>(sf + (r * 130 + xi) * SPADB + ci2 * 4) =
            *reinterpret_cast<uint32_t*>(&v2);
    }
    stage_w(sw, w1, 0, tid);
    __syncthreads();

    float acc[4][4][4];
    #pragma unroll
    for (int mf = 0; mf < 4; mf++)
        #pragma unroll
        for (int nf = 0; nf < 4; nf++)
            #pragma unroll
            for (int r = 0; r < 4; r++) acc[mf][nf][r] = 0.f;

    for (int t = 0; t < 9; t++) {
        if (t < 8) stage_w(sw + ((t + 1) & 1) * WBUF, w1, t + 1, tid);
        const char* wb = sw + (t & 1) * WBUF;
        const int ky = t / 3, kx = t - ky * 3;
        const char* frow = sf + ((rowsel + ky) * 130) * SPADB;

        #pragma unroll
        for (int kc = 0; kc < 4; kc++) {
            uint32_t afr[4][4];
            #pragma unroll
            for (int mf = 0; mf < 4; mf++) {
                const char* ap = frow
                    + (xwbase + mf * 16 + gid + kx) * SPADB
                    + kc * 32 + tig * 4;
                afr[mf][0] = *reinterpret_cast<const uint32_t*>(ap);
                afr[mf][1] = *reinterpret_cast<const uint32_t*>(ap + 8 * SPADB);
                afr[mf][2] = *reinterpret_cast<const uint32_t*>(ap + 16);
                afr[mf][3] = *reinterpret_cast<const uint32_t*>(ap + 8 * SPADB + 16);
            }
            #pragma unroll
            for (int nf = 0; nf < 4; nf++) {
                const int n = warpN * 32 + nf * 8 + gid;
                const char* bp = wb + n * SPADB + kc * 32 + tig * 4;
                uint32_t b0 = *reinterpret_cast<const uint32_t*>(bp);
                uint32_t b1 = *reinterpret_cast<const uint32_t*>(bp + 16);
                #pragma unroll
                for (int mf = 0; mf < 4; mf++)
                    mma_bf16(acc[mf][nf], afr[mf], b0, b1);
            }
        }
        __syncthreads();
    }

    // ---- Epilogue: ReLU + store h channel-last bf16 as bf16x2 words ----
    const int yy = y0 + rowsel;
    #pragma unroll
    for (int nf = 0; nf < 4; nf++) {
        const int co = warpN * 32 + nf * 8 + tig * 2;
        #pragma unroll
        for (int mf = 0; mf < 4; mf++) {
            const int xg = x0 + xwbase + mf * 16 + gid;
            size_t base = (((size_t)b * H_ + yy) * W_ + xg) * C_ + co;
            if (xg < W_) {
                __nv_bfloat162 v = __floats2bfloat162_rn(
                    fmaxf(acc[mf][nf][0], 0.f), fmaxf(acc[mf][nf][1], 0.f));
                *reinterpret_cast<uint32_t*>(&g_h[base]) =
                    *reinterpret_cast<uint32_t*>(&v);
            }
            if (xg + 8 < W_) {
                __nv_bfloat162 v = __floats2bfloat162_rn(
                    fmaxf(acc[mf][nf][2], 0.f), fmaxf(acc[mf][nf][3], 0.f));
                *reinterpret_cast<uint32_t*>(&g_h[base + 8 * C_]) =
                    *reinterpret_cast<uint32_t*>(&v);
            }
        }
    }
}

// ---------------------------------------------------------------------------
// Kernel B: 1x1 conv (64->144) via bf16 mma + softmax(9 taps) + depth blend
// + pixel shuffle. CTA = 64 px of one row, 256 threads (8 warps).
// Phase 1: GEMM M=64 N=144 K=64; warp grid 4M(16px) x 2N(72co = 9 nfrags).
// Logits -> smem [64 px][146 pad].  Phase 2: thread = 1 px x 4 cells of one
// s1-row -> softmax+blend in regs -> coalesced float4 store.
// ---------------------------------------------------------------------------
#define SHB_OFF   0            // h tile  [64 px][72 bf16]  9216 B
#define SWB_OFF   9216         // w2      [144 co][72 bf16] 20736 B
#define SLOG_OFF  29952        // logits  [64][146] f32     37376 B
#define SDEP_OFF  67328        // depth   [3][66] f32         792 B
#define SMEM_B_BYTES 68128

__global__ __launch_bounds__(256) void mask_upsample_kernel(
    const float* __restrict__ depth, const float* __restrict__ w2,
    float* __restrict__ out)
{
    extern __shared__ char smB[];
    char*  shb  = smB + SHB_OFF;
    char*  swb  = smB + SWB_OFF;
    float* slog = reinterpret_cast<float*>(smB + SLOG_OFF);
    float (*sdep)[66] = reinterpret_cast<float(*)[66]>(smB + SDEP_OFF);

    const int x0  = blockIdx.x * 64;
    const int y   = blockIdx.y;
    const int b   = blockIdx.z;
    const int tid = threadIdx.x;
    const int wid = tid >> 5;
    const int lane = tid & 31;
    const int gid = lane >> 2;
    const int tig = lane & 3;
    const int warpM = wid & 3;
    const int warpN = wid >> 2;

    // ---- Stage h tile: 64 px x 128 B (8 x uint4 per px), zeros past W ----
    for (int j = tid; j < 64 * 8; j += 256) {
        int px = j >> 3, seg = j & 7;
        int gx = x0 + px;
        uint4 v = make_uint4(0u, 0u, 0u, 0u);
        if (gx < W_)
            v = *reinterpret_cast<const uint4*>(
                g_h + ((((size_t)b * H_ + y) * W_ + gx) * C_ + seg * 8));
        *reinterpret_cast<uint4*>(shb + px * SPADB + seg * 16) = v;
    }
    // ---- Stage w2 as bf16 k-major [co][ci] ----
    for (int j = tid; j < 144 * 32; j += 256) {
        int co = j >> 5, ci2 = j & 31;
        const float* wp = w2 + co * 64 + ci2 * 2;
        __nv_bfloat162 v2 = __floats2bfloat162_rn(wp[0], wp[1]);
        *reinterpret_cast<uint32_t*>(swb + co * SPADB + ci2 * 4) =
            *reinterpret_cast<uint32_t*>(&v2);
    }
    for (int i = tid; i < 3 * 66; i += 256) {
        int ry = i / 66, rx = i - ry * 66;
        int gy = y + ry - 1, gx = x0 + rx - 1;
        sdep[ry][rx] = (gy >= 0 && gy < H_ && gx >= 0 && gx < W_)
                       ? depth[((size_t)b * H_ + gy) * W_ + gx] : 0.f;
    }
    __syncthreads();

    // ---- Phase 1: GEMM -> logits ----
    float acc[9][4];
    #pragma unroll
    for (int nf = 0; nf < 9; nf++)
        #pragma unroll
        for (int r = 0; r < 4; r++) acc[nf][r] = 0.f;

    #pragma unroll
    for (int kc = 0; kc < 4; kc++) {
        uint32_t a[4];
        const char* ap = shb + (warpM * 16 + gid) * SPADB + kc * 32 + tig * 4;
        a[0] = *reinterpret_cast<const uint32_t*>(ap);
        a[1] = *reinterpret_cast<const uint32_t*>(ap + 8 * SPADB);
        a[2] = *reinterpret_cast<const uint32_t*>(ap + 16);
        a[3] = *reinterpret_cast<const uint32_t*>(ap + 8 * SPADB + 16);
        #pragma unroll
        for (int nf = 0; nf < 9; nf++) {
            const int co = warpN * 72 + nf * 8 + gid;
            const char* bp = swb + co * SPADB + kc * 32 + tig * 4;
            uint32_t b0 = *reinterpret_cast<const uint32_t*>(bp);
            uint32_t b1 = *reinterpret_cast<const uint32_t*>(bp + 16);
            mma_bf16(acc[nf], a, b0, b1);
        }
    }

    // Scatter logits to smem: [px][co], stride 146 (2-way-safe, 8B aligned)
    {
        const int px = warpM * 16 + gid;
        #pragma unroll
        for (int nf = 0; nf < 9; nf++) {
            const int co = warpN * 72 + nf * 8 + tig * 2;
            *reinterpret_cast<float2*>(&slog[px * 146 + co]) =
                make_float2(acc[nf][0], acc[nf][1]);
            *reinterpret_cast<float2*>(&slog[(px + 8) * 146 + co]) =
                make_float2(acc[nf][2], acc[nf][3]);
        }
    }
    __syncthreads();

    // ---- Phase 2: softmax over taps + depth blend + pixel shuffle ----
    const int px   = tid & 63;
    const int cgrp = tid >> 6;          // s1 row; cells cgrp*4 .. cgrp*4+3
    float d[9];
    #pragma unroll
    for (int t = 0; t < 9; t++) d[t] = sdep[t / 3][px + (t % 3)];

    float vals[4];
    #pragma unroll
    for (int j = 0; j < 4; j++) {
        const int cell = cgrp * 4 + j;
        float lg[9];
        #pragma unroll
        for (int t = 0; t < 9; t++) lg[t] = slog[px * 146 + t * 16 + cell];
        float mx = lg[0];
        #pragma unroll
        for (int t = 1; t < 9; t++) mx = fmaxf(mx, lg[t]);
        float s = 0.f, v = 0.f;
        #pragma unroll
        for (int t = 0; t < 9; t++) {
            float e = __expf(lg[t] - mx);
            s += e;
            v = fmaf(e, d[t], v);
        }
        vals[j] = v / s;
    }

    const int gx = x0 + px;
    if (gx < W_)
        *reinterpret_cast<float4*>(
            &out[((size_t)b * OH_ + (y * 4 + cgrp)) * OW_ + gx * 4]) =
            make_float4(vals[0], vals[1], vals[2], vals[3]);
}

extern "C" void kernel_launch(void* const* d_in, const int* in_sizes, int n_in,
                              void* d_out, int out_size)
{
    const float* depth = (const float*)d_in[0];
    const float* feat  = (const float*)d_in[1];
    const float* w1    = (const float*)d_in[2];
    const float* w2    = (const float*)d_in[3];
    float* out = (float*)d_out;

    cudaFuncSetAttribute(conv3x3_tc_kernel,
                         cudaFuncAttributeMaxDynamicSharedMemorySize, SMEM_A_BYTES);
    cudaFuncSetAttribute(mask_upsample_kernel,
                         cudaFuncAttributeMaxDynamicSharedMemorySize, SMEM_B_BYTES);

    dim3 gA(4, H_ / 2, B_);                   // 4 x-tiles x 64 row-pairs x 8
    conv3x3_tc_kernel<<<gA, 256, SMEM_A_BYTES>>>(feat, w1);

    dim3 gB((W_ + 63) / 64, H_, B_);          // 7 x-tiles of 64 px
    mask_upsample_kernel<<<gB, 256, SMEM_B_BYTES>>>(depth, w2, out);
}

// round 8
// speedup vs baseline: 5.2163x; 1.0948x over previous
#include <cuda_runtime.h>
#include <cuda_bf16.h>
#include <cstdint>

#define B_   8
#define C_   64
#define H_   128
#define W_   416
#define OH_  (4 * H_)
#define OW_  (4 * W_)
#define HW_  (H_ * W_)

// Scratch h: conv3x3+relu output, CHANNEL-LAST bf16: [b][y][x][ci] (~54.5 MB).
__device__ __nv_bfloat16 g_h[(size_t)B_ * H_ * W_ * C_];

// ---------------------------------------------------------------------------
// helpers (legacy mma.sync / ldmatrix — compile for plain compute_103)
// ---------------------------------------------------------------------------
__device__ __forceinline__ uint32_t smem_u32(const void* p) {
    uint32_t a;
    asm("{ .reg .u64 t; cvta.to.shared.u64 t, %1; cvt.u32.u64 %0, t; }"
        : "=r"(a) : "l"(p));
    return a;
}

__device__ __forceinline__ void mma_bf16(float* d, const uint32_t* a,
                                         uint32_t b0, uint32_t b1) {
    asm volatile(
        "mma.sync.aligned.m16n8k16.row.col.f32.bf16.bf16.f32 "
        "{%0,%1,%2,%3}, {%4,%5,%6,%7}, {%8,%9}, {%0,%1,%2,%3};"
        : "+f"(d[0]), "+f"(d[1]), "+f"(d[2]), "+f"(d[3])
        : "r"(a[0]), "r"(a[1]), "r"(a[2]), "r"(a[3]), "r"(b0), "r"(b1));
}

__device__ __forceinline__ void ldmx4(uint32_t* r, uint32_t addr) {
    asm volatile(
        "ldmatrix.sync.aligned.m8n8.x4.shared.b16 {%0,%1,%2,%3}, [%4];"
        : "=r"(r[0]), "=r"(r[1]), "=r"(r[2]), "=r"(r[3]) : "r"(addr));
}

// ---------------------------------------------------------------------------
// Kernel A: conv3x3 (pad=1, no bias) + ReLU as bf16 implicit GEMM.
// CTA = 4 rows x 128 px x 64 co, 512 threads (16 warps: 8 M-warps x 2 N-warps).
// All 9 taps of weights + 6 feat rows staged ONCE -> zero mainloop syncs.
// Fragments via ldmatrix.x4 (row stride 144 B: conflict-free).
// ---------------------------------------------------------------------------
#define SPADB  144                      // bytes per ci-row (72 bf16 slots)
#define OFF_W  112320                   // feat: 6*130*144
#define WTAP   9216                     // per-tap weights: 64*144
#define SMEM_A_BYTES (112320 + 9 * 9216)   // 195264

__global__ __launch_bounds__(512, 1) void conv3x3_tc_kernel(
    const float* __restrict__ feat, const float* __restrict__ w1)
{
    extern __shared__ char sm[];
    const uint32_t sbase = smem_u32(sm);

    const int x0  = (blockIdx.x < 3) ? blockIdx.x * 128 : (W_ - 128);
    const int y0  = blockIdx.y * 4;
    const int b   = blockIdx.z;
    const int tid = threadIdx.x;
    const int wid = tid >> 5;
    const int lane = tid & 31;
    const int gid = lane >> 2;
    const int tig = lane & 3;

    const int warpM  = wid & 7;          // 8 M-warps
    const int warpN  = wid >> 3;         // 2 N-warps x 32 co
    const int rowsel = warpM >> 1;       // output row 0..3
    const int xwbase = (warpM & 1) * 64;

    // ---- Stage feat rows y0-1 .. y0+4 as bf16 pairs, [r][xi][ci] ----
    for (int j = tid; j < 6 * 32 * 130; j += 512) {
        int r   = j / (32 * 130);
        int rem = j - r * (32 * 130);
        int ci2 = rem / 130;
        int xi  = rem - ci2 * 130;
        int yy  = y0 + r - 1;
        int gx  = x0 + xi - 1;
        float f0 = 0.f, f1 = 0.f;
        if ((unsigned)yy < (unsigned)H_ && (unsigned)gx < (unsigned)W_) {
            size_t o = ((size_t)(b * C_ + 2 * ci2) * H_ + yy) * W_ + gx;
            f0 = feat[o];
            f1 = feat[o + (size_t)HW_];
        }
        __nv_bfloat162 v2 = __floats2bfloat162_rn(f0, f1);
        *reinterpret_cast<uint32_t*>(sm + (r * 130 + xi) * SPADB + ci2 * 4) =
            *reinterpret_cast<uint32_t*>(&v2);
    }
    // ---- Stage ALL 9 taps of w1 as bf16 [tap][co][ci] ----
    for (int j = tid; j < 9 * 64 * 32; j += 512) {
        int tap = j >> 11;
        int co  = (j >> 5) & 63;
        int ci2 = j & 31;
        const float* wp = w1 + co * 576 + ci2 * 18 + tap;
        __nv_bfloat162 v2 = __floats2bfloat162_rn(wp[0], wp[9]);
        *reinterpret_cast<uint32_t*>(sm + OFF_W + tap * WTAP + co * SPADB + ci2 * 4) =
            *reinterpret_cast<uint32_t*>(&v2);
    }
    __syncthreads();

    // per-lane ldmatrix offsets
    const uint32_t a_loff = (uint32_t)(((lane & 7) + ((lane >> 3) & 1) * 8) * SPADB
                                       + ((lane >> 4) & 1) * 16);
    const uint32_t b_loff = (uint32_t)((lane & 7) * SPADB + ((lane >> 3) & 1) * 16
                                       + ((lane >> 4) & 1) * (8 * SPADB));

    float acc[4][4][4];
    #pragma unroll
    for (int mf = 0; mf < 4; mf++)
        #pragma unroll
        for (int nf = 0; nf < 4; nf++)
            #pragma unroll
            for (int r = 0; r < 4; r++) acc[mf][nf][r] = 0.f;

    #pragma unroll
    for (int t = 0; t < 9; t++) {
        const int ky = t / 3, kx = t - ky * 3;
        const uint32_t frow = sbase
            + (uint32_t)(((rowsel + ky) * 130 + xwbase + kx) * SPADB) + a_loff;
        const uint32_t wrow = sbase + OFF_W + (uint32_t)(t * WTAP)
            + (uint32_t)(warpN * 32 * SPADB) + b_loff;

        #pragma unroll
        for (int kc = 0; kc < 4; kc++) {
            uint32_t a[4][4];
            #pragma unroll
            for (int mf = 0; mf < 4; mf++)
                ldmx4(a[mf], frow + (uint32_t)(mf * 16 * SPADB + kc * 32));
            uint32_t bf[8];
            ldmx4(bf,     wrow + (uint32_t)(kc * 32));
            ldmx4(bf + 4, wrow + (uint32_t)(16 * SPADB + kc * 32));
            #pragma unroll
            for (int nf = 0; nf < 4; nf++)
                #pragma unroll
                for (int mf = 0; mf < 4; mf++)
                    mma_bf16(acc[mf][nf], a[mf], bf[nf * 2], bf[nf * 2 + 1]);
        }
    }

    // ---- Epilogue: ReLU + store h channel-last bf16 as bf16x2 words ----
    const int yy = y0 + rowsel;
    #pragma unroll
    for (int nf = 0; nf < 4; nf++) {
        const int co = warpN * 32 + nf * 8 + tig * 2;
        #pragma unroll
        for (int mf = 0; mf < 4; mf++) {
            const int xg = x0 + xwbase + mf * 16 + gid;
            size_t base = (((size_t)b * H_ + yy) * W_ + xg) * C_ + co;
            if (xg < W_) {
                __nv_bfloat162 v = __floats2bfloat162_rn(
                    fmaxf(acc[mf][nf][0], 0.f), fmaxf(acc[mf][nf][1], 0.f));
                *reinterpret_cast<uint32_t*>(&g_h[base]) =
                    *reinterpret_cast<uint32_t*>(&v);
            }
            if (xg + 8 < W_) {
                __nv_bfloat162 v = __floats2bfloat162_rn(
                    fmaxf(acc[mf][nf][2], 0.f), fmaxf(acc[mf][nf][3], 0.f));
                *reinterpret_cast<uint32_t*>(&g_h[base + 8 * C_]) =
                    *reinterpret_cast<uint32_t*>(&v);
            }
        }
    }
}

// ---------------------------------------------------------------------------
// Kernel B: 1x1 conv (64->144) via bf16 mma + softmax(9 taps) + depth blend
// + pixel shuffle. CTA = 64 px of one row, 256 threads (8 warps).
// ---------------------------------------------------------------------------
#define SHB_OFF   0            // h tile  [64 px][72 bf16]  9216 B
#define SWB_OFF   9216         // w2      [144 co][72 bf16] 20736 B
#define SLOG_OFF  29952        // logits  [64][146] f32     37376 B
#define SDEP_OFF  67328        // depth   [3][66] f32         792 B
#define SMEM_B_BYTES 68128

__global__ __launch_bounds__(256) void mask_upsample_kernel(
    const float* __restrict__ depth, const float* __restrict__ w2,
    float* __restrict__ out)
{
    extern __shared__ char smB[];
    char*  shb  = smB + SHB_OFF;
    char*  swb  = smB + SWB_OFF;
    float* slog = reinterpret_cast<float*>(smB + SLOG_OFF);
    float (*sdep)[66] = reinterpret_cast<float(*)[66]>(smB + SDEP_OFF);

    const int x0  = (blockIdx.x < 6) ? blockIdx.x * 64 : (W_ - 64);
    const int y   = blockIdx.y;
    const int b   = blockIdx.z;
    const int tid = threadIdx.x;
    const int wid = tid >> 5;
    const int lane = tid & 31;
    const int gid = lane >> 2;
    const int tig = lane & 3;
    const int warpM = wid & 3;
    const int warpN = wid >> 2;

    for (int j = tid; j < 64 * 8; j += 256) {
        int px = j >> 3, seg = j & 7;
        int gx = x0 + px;
        uint4 v = make_uint4(0u, 0u, 0u, 0u);
        if (gx < W_)
            v = *reinterpret_cast<const uint4*>(
                g_h + ((((size_t)b * H_ + y) * W_ + gx) * C_ + seg * 8));
        *reinterpret_cast<uint4*>(shb + px * SPADB + seg * 16) = v;
    }
    for (int j = tid; j < 144 * 32; j += 256) {
        int co = j >> 5, ci2 = j & 31;
        const float* wp = w2 + co * 64 + ci2 * 2;
        __nv_bfloat162 v2 = __floats2bfloat162_rn(wp[0], wp[1]);
        *reinterpret_cast<uint32_t*>(swb + co * SPADB + ci2 * 4) =
            *reinterpret_cast<uint32_t*>(&v2);
    }
    for (int i = tid; i < 3 * 66; i += 256) {
        int ry = i / 66, rx = i - ry * 66;
        int gy = y + ry - 1, gx = x0 + rx - 1;
        sdep[ry][rx] = (gy >= 0 && gy < H_ && gx >= 0 && gx < W_)
                       ? depth[((size_t)b * H_ + gy) * W_ + gx] : 0.f;
    }
    __syncthreads();

    float acc[9][4];
    #pragma unroll
    for (int nf = 0; nf < 9; nf++)
        #pragma unroll
        for (int r = 0; r < 4; r++) acc[nf][r] = 0.f;

    #pragma unroll
    for (int kc = 0; kc < 4; kc++) {
        uint32_t a[4];
        const char* ap = shb + (warpM * 16 + gid) * SPADB + kc * 32 + tig * 4;
        a[0] = *reinterpret_cast<const uint32_t*>(ap);
        a[1] = *reinterpret_cast<const uint32_t*>(ap + 8 * SPADB);
        a[2] = *reinterpret_cast<const uint32_t*>(ap + 16);
        a[3] = *reinterpret_cast<const uint32_t*>(ap + 8 * SPADB + 16);
        #pragma unroll
        for (int nf = 0; nf < 9; nf++) {
            const int co = warpN * 72 + nf * 8 + gid;
            const char* bp = swb + co * SPADB + kc * 32 + tig * 4;
            uint32_t b0 = *reinterpret_cast<const uint32_t*>(bp);
            uint32_t b1 = *reinterpret_cast<const uint32_t*>(bp + 16);
            mma_bf16(acc[nf], a, b0, b1);
        }
    }

    {
        const int px = warpM * 16 + gid;
        #pragma unroll
        for (int nf = 0; nf < 9; nf++) {
            const int co = warpN * 72 + nf * 8 + tig * 2;
            *reinterpret_cast<float2*>(&slog[px * 146 + co]) =
                make_float2(acc[nf][0], acc[nf][1]);
            *reinterpret_cast<float2*>(&slog[(px + 8) * 146 + co]) =
                make_float2(acc[nf][2], acc[nf][3]);
        }
    }
    __syncthreads();

    const int px   = tid & 63;
    const int cgrp = tid >> 6;
    float d[9];
    #pragma unroll
    for (int t = 0; t < 9; t++) d[t] = sdep[t / 3][px + (t % 3)];

    float vals[4];
    #pragma unroll
    for (int j = 0; j < 4; j++) {
        const int cell = cgrp * 4 + j;
        float lg[9];
        #pragma unroll
        for (int t = 0; t < 9; t++) lg[t] = slog[px * 146 + t * 16 + cell];
        float mx = lg[0];
        #pragma unroll
        for (int t = 1; t < 9; t++) mx = fmaxf(mx, lg[t]);
        float s = 0.f, v = 0.f;
        #pragma unroll
        for (int t = 0; t < 9; t++) {
            float e = __expf(lg[t] - mx);
            s += e;
            v = fmaf(e, d[t], v);
        }
        vals[j] = v / s;
    }

    const int gx = x0 + px;
    if (gx < W_)
        *reinterpret_cast<float4*>(
            &out[((size_t)b * OH_ + (y * 4 + cgrp)) * OW_ + gx * 4]) =
            make_float4(vals[0], vals[1], vals[2], vals[3]);
}

extern "C" void kernel_launch(void* const* d_in, const int* in_sizes, int n_in,
                              void* d_out, int out_size)
{
    const float* depth = (const float*)d_in[0];
    const float* feat  = (const float*)d_in[1];
    const float* w1    = (const float*)d_in[2];
    const float* w2    = (const float*)d_in[3];
    float* out = (float*)d_out;

    cudaFuncSetAttribute(conv3x3_tc_kernel,
                         cudaFuncAttributeMaxDynamicSharedMemorySize, SMEM_A_BYTES);
    cudaFuncSetAttribute(mask_upsample_kernel,
                         cudaFuncAttributeMaxDynamicSharedMemorySize, SMEM_B_BYTES);

    dim3 gA(4, H_ / 4, B_);                   // 4 x-tiles x 32 y-tiles x 8
    conv3x3_tc_kernel<<<gA, 512, SMEM_A_BYTES>>>(feat, w1);

    dim3 gB(7, H_, B_);                       // 7 x-tiles of 64 px (last clamped)
    mask_upsample_kernel<<<gB, 256, SMEM_B_BYTES>>>(depth, w2, out);
}